// round 13
// baseline (speedup 1.0000x reference)
#include <cuda_runtime.h>
#include <cuda_bf16.h>

// SimplifiedMambaBlock: reference SSM scan has no input-injection term
// (h0 = 0, h <- exp(dt*A) * h) => h == 0 always => result == x exactly.
// Optimal kernel = copy x -> d_out (33.5 MB fp32, rel_err = 0).
//
// R13: last falsification probe of the "memory-system floor" model. All
// prior probes used ONE engine at a time (SM-LDG, CE, TMA), each landing
// at ~6.4 TB/s. If that is a per-engine cap rather than the HBM mixed-R/W
// cap, running SM and CE CONCURRENTLY on disjoint halves scales ~2x.
// Fork/join with events (capture-legal multi-stream graph pattern):
//   legacy stream:  [evt fork] -> SM kernel (first half) -> [wait join]
//   side stream:            \-> CE memcpy (second half) -> [evt join]/
// Model-consistent outcome: neutral (shared HBM). Falsifying: ~8 us.

__global__ __launch_bounds__(256) void mamba_identity_copy4_half(
    const float4* __restrict__ src, float4* __restrict__ dst, int n4)
{
    int base = blockIdx.x * (blockDim.x * 4) + threadIdx.x;

    if (base + 3 * blockDim.x < n4) {
        float4 a = src[base];
        float4 b = src[base + blockDim.x];
        float4 c = src[base + 2 * blockDim.x];
        float4 d = src[base + 3 * blockDim.x];
        dst[base]                  = a;
        dst[base + blockDim.x]     = b;
        dst[base + 2 * blockDim.x] = c;
        dst[base + 3 * blockDim.x] = d;
    } else {
        #pragma unroll
        for (int k = 0; k < 4; k++) {
            int i = base + k * blockDim.x;
            if (i < n4) dst[i] = src[i];
        }
    }
}

extern "C" void kernel_launch(void* const* d_in, const int* in_sizes, int n_in,
                              void* d_out, int out_size)
{
    const float* x = (const float*)d_in[0];   // (B, L, dim) fp32
    float* out = (float*)d_out;

    // Split: first half -> SM kernel, second half -> CE memcpy, concurrent.
    int n  = out_size;            // 8388608 floats
    int nh = n >> 1;              // 4194304 floats per half
    int n4 = nh >> 2;             // 1048576 float4 in SM half

    // Host-side stream/event creation (not device memory; capture-legal).
    cudaStream_t s2;
    cudaStreamCreate(&s2);
    cudaEvent_t e_fork, e_join;
    cudaEventCreateWithFlags(&e_fork, cudaEventDisableTiming);
    cudaEventCreateWithFlags(&e_join, cudaEventDisableTiming);

    // Fork: side stream joins the capture after this point.
    cudaEventRecord(e_fork, 0);
    cudaStreamWaitEvent(s2, e_fork, 0);

    // CE engine: second half on side stream.
    cudaMemcpyAsync(out + nh, x + nh, (size_t)nh * sizeof(float),
                    cudaMemcpyDeviceToDevice, s2);

    // SM engine: first half on the capture (legacy) stream.
    int threads = 256;
    int per_block = threads * 4;
    int blocks = (n4 + per_block - 1) / per_block;   // 1024
    mamba_identity_copy4_half<<<blocks, threads>>>(
        (const float4*)x, (float4*)out, n4);

    // Join: capture stream waits for the CE branch.
    cudaEventRecord(e_join, s2);
    cudaStreamWaitEvent(0, e_join, 0);

    // Handles may be destroyed immediately; captured graph keeps the deps.
    cudaEventDestroy(e_fork);
    cudaEventDestroy(e_join);
    cudaStreamDestroy(s2);
}

// round 14
// speedup vs baseline: 1.1195x; 1.1195x over previous
#include <cuda_runtime.h>
#include <cuda_bf16.h>

// SimplifiedMambaBlock — FINAL (converged).
//
// Math: the reference SSM scan has no input-injection term (h0 = 0,
// h <- exp(dt*A) * h, dt=softplus>=0, A<=0), so h == 0 for every timestep,
// ssm_out == 0, y = 0*z == 0, out_proj(0) == 0, and the result is exactly
// `x + residual == x`. Exact-optimal kernel = copy x -> d_out
// (33.5 MB fp32, rel_err = 0 algebraically).
//
// Perf: full probe matrix over 12 rounds —
//   SM-LDG variants (vector width, MLP, grid shape, persistent one-wave),
//   copy-engine memcpy node, TMA bulk G->SMEM->G, L2::evict_last policies,
//   streaming .cs stores, and concurrent SM||CE split —
// converges at 10.4-11.0 us single-engine (±0.5 us identical-binary
// variance), with .cs stores 2x worse (forfeits L2 write coalescing) and
// SM||CE worse (shared HBM + fork/join overhead). Floor model:
//   67 MB mandatory 1:1 R/W traffic / ~6.4 TB/s sustained mixed-R/W HBM
//   rate (bus turnaround; ~80% of the 8 TB/s read-only headline)
//   + ~0.5 us launch/tail  ==  observed band.
// This config was the best measured: 10.43 us.

__global__ __launch_bounds__(256) void mamba_identity_copy4(
    const float4* __restrict__ src, float4* __restrict__ dst, int n4)
{
    // Block-linear: each block owns a contiguous 4*256 = 1024-float4 chunk.
    int base = blockIdx.x * (blockDim.x * 4) + threadIdx.x;

    if (base + 3 * blockDim.x < n4) {
        // Fast path: 4 independent loads issued back-to-back (MLP=4).
        float4 a = src[base];
        float4 b = src[base + blockDim.x];
        float4 c = src[base + 2 * blockDim.x];
        float4 d = src[base + 3 * blockDim.x];
        dst[base]                  = a;
        dst[base + blockDim.x]     = b;
        dst[base + 2 * blockDim.x] = c;
        dst[base + 3 * blockDim.x] = d;
    } else {
        #pragma unroll
        for (int k = 0; k < 4; k++) {
            int i = base + k * blockDim.x;
            if (i < n4) dst[i] = src[i];
        }
    }
}

extern "C" void kernel_launch(void* const* d_in, const int* in_sizes, int n_in,
                              void* d_out, int out_size)
{
    const float* x = (const float*)d_in[0];   // (B, L, dim) fp32
    float* out = (float*)d_out;

    int n4 = out_size >> 2;                   // 2097152 float4
    int threads = 256;
    int per_block = threads * 4;              // 1024 float4 per block
    int blocks = (n4 + per_block - 1) / per_block;  // 2048

    mamba_identity_copy4<<<blocks, threads>>>(
        (const float4*)x, (float4*)out, n4);
}

// round 15
// speedup vs baseline: 1.1228x; 1.0029x over previous
#include <cuda_runtime.h>
#include <cuda_bf16.h>

// SimplifiedMambaBlock — FINAL (converged; do not churn further).
//
// Math: the reference SSM scan has no input-injection term (h0 = 0,
// h <- exp(dt*A) * h, dt=softplus>=0, A<=0), so h == 0 for every timestep,
// ssm_out == 0, y = 0*z == 0, out_proj(0) == 0, and the result is exactly
// `x + residual == x`. Exact-optimal kernel = copy x -> d_out
// (33.5 MB fp32, rel_err = 0 algebraically).
//
// Perf evidence (13 rounds):
//   - SM-LDG (f4x1/f4x4/LDG.256, 1-wave persistent, grid shapes),
//     copy-engine memcpy node, and TMA bulk G->SMEM->G all converge at
//     10.4-11.0 us; identical-binary spread is ±0.5 us.
//   - Concurrent SM||CE split: 12.3 us (shared HBM + fork/join overhead).
//   - L2::evict_last (either or both streams): neutral — replay-to-replay
//     L2 residency is unattainable under this harness.
//   - st.global.cs streaming stores: 20.1 us (forfeits L2 write coalescing).
// Floor model: 67 MB mandatory 1:1 R/W traffic / ~6.4 TB/s sustained
// mixed-R/W HBM rate (bus turnaround; ~80% of the 8 TB/s read-only
// headline) + ~0.5 us launch/tail == the observed band. Traffic is
// algebraically irreducible, so this is the problem's true floor.
//
// Config: 4x float4 per thread, front-batched loads (MLP=4), 2048x256.
// Best measured 10.43 us; distribution center ~10.9 us.

__global__ __launch_bounds__(256) void mamba_identity_copy4(
    const float4* __restrict__ src, float4* __restrict__ dst, int n4)
{
    // Block-linear: each block owns a contiguous 4*256 = 1024-float4 chunk.
    int base = blockIdx.x * (blockDim.x * 4) + threadIdx.x;

    if (base + 3 * blockDim.x < n4) {
        // Fast path: 4 independent loads issued back-to-back (MLP=4).
        float4 a = src[base];
        float4 b = src[base + blockDim.x];
        float4 c = src[base + 2 * blockDim.x];
        float4 d = src[base + 3 * blockDim.x];
        dst[base]                  = a;
        dst[base + blockDim.x]     = b;
        dst[base + 2 * blockDim.x] = c;
        dst[base + 3 * blockDim.x] = d;
    } else {
        #pragma unroll
        for (int k = 0; k < 4; k++) {
            int i = base + k * blockDim.x;
            if (i < n4) dst[i] = src[i];
        }
    }
}

extern "C" void kernel_launch(void* const* d_in, const int* in_sizes, int n_in,
                              void* d_out, int out_size)
{
    const float* x = (const float*)d_in[0];   // (B, L, dim) fp32
    float* out = (float*)d_out;

    int n4 = out_size >> 2;                   // 2097152 float4
    int threads = 256;
    int per_block = threads * 4;              // 1024 float4 per block
    int blocks = (n4 + per_block - 1) / per_block;  // 2048

    mamba_identity_copy4<<<blocks, threads>>>(
        (const float4*)x, (float4*)out, n4);
}

// round 16
// speedup vs baseline: 1.1463x; 1.0209x over previous
#include <cuda_runtime.h>
#include <cuda_bf16.h>

// SimplifiedMambaBlock — FINAL (converged across 14 rounds; holding).
//
// Math: the reference SSM scan has no input-injection term (h0 = 0,
// h <- exp(dt*A) * h, dt=softplus>=0, A<=0), so h == 0 for every timestep,
// ssm_out == 0, y = 0*z == 0, out_proj(0) == 0, and the result is exactly
// `x + residual == x`. Exact-optimal kernel = copy x -> d_out
// (33.5 MB fp32, rel_err = 0 algebraically).
//
// Perf evidence:
//   - Engines: SM-LDG variants, copy-engine memcpy node, TMA bulk
//     G->SMEM->G all converge at 10.4-11.0 us.
//   - Identical-binary samples: {10.43, 10.98, 10.98, 10.94, 10.98} —
//     ±0.5 us run-to-run noise, center ~10.95, floor-tail 10.43.
//   - Concurrent SM||CE split: 12.3 us (shared HBM + fork/join overhead).
//   - L2::evict_last (either/both streams): neutral — replay-to-replay L2
//     residency unattainable under this harness.
//   - st.global.cs streaming stores: 20.1 us (forfeits L2 write coalescing).
// Floor model: 67 MB mandatory 1:1 R/W traffic / ~6.4 TB/s sustained
// mixed-R/W HBM rate (bus-turnaround limited; ~80% of the 8 TB/s read-only
// headline) + ~0.5 us launch/tail == observed band. The traffic is
// algebraically irreducible; remaining "wins" would require making work
// depend on prior-replay output, which violates the harness determinism
// contract.
//
// Config: 4x float4 per thread, front-batched loads (MLP=4), 2048x256.

__global__ __launch_bounds__(256) void mamba_identity_copy4(
    const float4* __restrict__ src, float4* __restrict__ dst, int n4)
{
    // Block-linear: each block owns a contiguous 4*256 = 1024-float4 chunk.
    int base = blockIdx.x * (blockDim.x * 4) + threadIdx.x;

    if (base + 3 * blockDim.x < n4) {
        // Fast path: 4 independent loads issued back-to-back (MLP=4).
        float4 a = src[base];
        float4 b = src[base + blockDim.x];
        float4 c = src[base + 2 * blockDim.x];
        float4 d = src[base + 3 * blockDim.x];
        dst[base]                  = a;
        dst[base + blockDim.x]     = b;
        dst[base + 2 * blockDim.x] = c;
        dst[base + 3 * blockDim.x] = d;
    } else {
        #pragma unroll
        for (int k = 0; k < 4; k++) {
            int i = base + k * blockDim.x;
            if (i < n4) dst[i] = src[i];
        }
    }
}

extern "C" void kernel_launch(void* const* d_in, const int* in_sizes, int n_in,
                              void* d_out, int out_size)
{
    const float* x = (const float*)d_in[0];   // (B, L, dim) fp32
    float* out = (float*)d_out;

    int n4 = out_size >> 2;                   // 2097152 float4
    int threads = 256;
    int per_block = threads * 4;              // 1024 float4 per block
    int blocks = (n4 + per_block - 1) / per_block;  // 2048

    mamba_identity_copy4<<<blocks, threads>>>(
        (const float4*)x, (float4*)out, n4);
}